// round 12
// baseline (speedup 1.0000x reference)
#include <cuda_runtime.h>
#include <cuda_fp16.h>

#define Hh 96
#define Ww 96
#define TPB 384      // 12 warps: 3 M-strips (x32 rows) x 4 N-strips (x24 cols)
#define PAD 104      // halfs per smem row (208B stride: conflict-free ldmatrix)

typedef unsigned int u32;

static __device__ __forceinline__ u32 smem_u32(const void* p) {
    u32 a;
    asm("{ .reg .u64 t; cvta.to.shared.u64 t, %1; cvt.u32.u64 %0, t; }" : "=r"(a) : "l"(p));
    return a;
}

__global__ __launch_bounds__(TPB, 3) void conv_mma_kernel(
    const float* __restrict__ x, const float* __restrict__ pe,
    const float* __restrict__ wt, const float* __restrict__ bias,
    const float* __restrict__ rw, float* __restrict__ out, int C)
{
    // As (96x104 half) + Bs (96x104 half) = 39936B; reused as Os (96x104 float) in epilogue
    __shared__ __align__(16) char sbuf[2 * Hh * PAD * 2];
    __shared__ __align__(16) __half wcdS[4][192];   // shift-replicated combined weights

    __half* As = (__half*)sbuf;                 // circulant weights, M x K row-major
    __half* Bs = (__half*)sbuf + Hh * PAD;      // x + pe, K x N row-major

    const int t  = threadIdx.x;
    const int bc = blockIdx.x;          // b*C + c
    const int c  = bc % C;

    const float* xp  = x + (size_t)bc * (Hh * Ww);
    const float* pep = pe + c * Hh;

    // Shift-replicated combined weights: wcdS[r][i] = wc[(i+r) mod 96], periodic in i.
    // Enables one aligned LDS.64 in the A-fill (idx mod 4 == (-h) mod 4, constant per row).
    {
        int r = t / 96, i0 = t % 96;            // t < 384 covers all (r, i0)
        int k = (i0 + r) % Hh;
        float w = wt[c * Hh + k] + (k < 3 ? rw[c * 3 + k] : 0.0f);
        __half hv = __float2half_rn(w);
        wcdS[r][i0] = hv; wcdS[r][i0 + 96] = hv;
    }

    // B fill: Bs[k][n] = fp16(x[k][n] + pe[k]),  K x N row-major, PAD stride
    #pragma unroll
    for (int i = t; i < (Hh * Ww) / 4; i += TPB) {
        float4 v = ((const float4*)xp)[i];
        int k = i / 24, n0 = (i % 24) * 4;
        float p = pep[k];
        __half2 h01 = __floats2half2_rn(v.x + p, v.y + p);
        __half2 h23 = __floats2half2_rn(v.z + p, v.w + p);
        *(uint2*)&Bs[k * PAD + n0] = make_uint2(*(u32*)&h01, *(u32*)&h23);
    }
    __syncthreads();

    // A fill: As[h][j0..j0+3] = wcdbig[idx..idx+3], idx = j0-h+96.
    // r = idx&3, base = idx-r: wcdS[r][base+m] == wcdbig[idx+m] -> one aligned LDS.64.
    #pragma unroll
    for (int i = t; i < (Hh * Ww) / 4; i += TPB) {
        int h = i / 24, j0 = (i % 24) * 4;
        int idx = j0 - h + 96;                   // in [1,188]
        int r = idx & 3, base = idx - r;
        uint2 w4 = *(const uint2*)&wcdS[r][base];
        *(uint2*)&As[h * PAD + j0] = w4;
    }
    __syncthreads();

    // warp tiling: 32(M) x 24(N) per warp; B-frag shared by both m16-frags
    const int wid = t >> 5, lane = t & 31;
    const int mrow = (wid >> 2) * 32;       // 3 M-strips
    const int ncol = (wid & 3) * 24;        // 4 N-strips
    const int lr = lane & 15, lc = lane >> 4;

    const u32 sA = smem_u32(As), sB = smem_u32(Bs);
    const float bv = bias[c];

    float acc[2][3][4];
    #pragma unroll
    for (int mf = 0; mf < 2; mf++)
        #pragma unroll
        for (int n = 0; n < 3; n++)
            #pragma unroll
            for (int q = 0; q < 4; q++) acc[mf][n][q] = bv;   // bias in acc init

    #pragma unroll
    for (int k6 = 0; k6 < 6; k6++) {
        u32 a[2][4];
        #pragma unroll
        for (int mf = 0; mf < 2; mf++) {
            u32 aaddr = sA + (u32)((mrow + mf * 16 + lr) * PAD + k6 * 16 + lc * 8) * 2;
            asm volatile("ldmatrix.sync.aligned.m8n8.x4.shared.b16 {%0,%1,%2,%3}, [%4];"
                         : "=r"(a[mf][0]), "=r"(a[mf][1]), "=r"(a[mf][2]), "=r"(a[mf][3])
                         : "r"(aaddr));
        }
        #pragma unroll
        for (int n = 0; n < 3; n++) {
            u32 b0, b1;
            u32 baddr = sB + (u32)((k6 * 16 + lr) * PAD + ncol + n * 8) * 2;
            asm volatile("ldmatrix.sync.aligned.m8n8.x2.trans.shared.b16 {%0,%1}, [%2];"
                         : "=r"(b0), "=r"(b1) : "r"(baddr));
            #pragma unroll
            for (int mf = 0; mf < 2; mf++)
                asm volatile(
                    "mma.sync.aligned.m16n8k16.row.col.f32.f16.f16.f32 "
                    "{%0,%1,%2,%3}, {%4,%5,%6,%7}, {%8,%9}, {%0,%1,%2,%3};"
                    : "+f"(acc[mf][n][0]), "+f"(acc[mf][n][1]),
                      "+f"(acc[mf][n][2]), "+f"(acc[mf][n][3])
                    : "r"(a[mf][0]), "r"(a[mf][1]), "r"(a[mf][2]), "r"(a[mf][3]),
                      "r"(b0), "r"(b1));
        }
    }

    // ---- staged epilogue: acc -> smem (stride 104 floats) -> coalesced STG.128 ----
    __syncthreads();                         // all ldmatrix reads done; safe to reuse sbuf
    float* Os = (float*)sbuf;                // 96 x 104 floats = 39936B (exact fit)
    const int rbase = mrow + (lane >> 2);
    const int col0  = ncol + (lane & 3) * 2;
    #pragma unroll
    for (int mf = 0; mf < 2; mf++) {
        const int row = rbase + mf * 16;
        #pragma unroll
        for (int n = 0; n < 3; n++) {
            *(float2*)&Os[row * PAD + col0 + n * 8]       = make_float2(acc[mf][n][0], acc[mf][n][1]);
            *(float2*)&Os[(row + 8) * PAD + col0 + n * 8] = make_float2(acc[mf][n][2], acc[mf][n][3]);
        }
    }
    __syncthreads();

    float* op = out + (size_t)bc * (Hh * Ww);
    #pragma unroll
    for (int i = t; i < (Hh * Ww) / 4; i += TPB) {
        int row = i / 24, c4 = (i % 24) * 4;
        float4 v = *(const float4*)&Os[row * PAD + c4];
        ((float4*)op)[i] = v;
    }
}

extern "C" void kernel_launch(void* const* d_in, const int* in_sizes, int n_in,
                              void* d_out, int out_size) {
    const float* x    = (const float*)d_in[0];
    const float* pe   = (const float*)d_in[1];
    const float* wt   = (const float*)d_in[2];
    const float* bias = (const float*)d_in[3];
    const float* rw   = (const float*)d_in[4];
    float* out = (float*)d_out;

    const int nblocks = in_sizes[0] / (Hh * Ww);  // B*C = 4096
    const int C       = in_sizes[2] / Hh;         // 256

    conv_mma_kernel<<<nblocks, TPB>>>(x, pe, wt, bias, rw, out, C);
}

// round 14
// speedup vs baseline: 1.4282x; 1.4282x over previous
#include <cuda_runtime.h>
#include <cuda_fp16.h>

#define Hh 96
#define Ww 96
#define TPB 384      // 12 warps: 3 M-strips (x32 rows) x 4 N-strips (x24 cols)
#define PAD 104      // halfs per smem row (208B stride: conflict-free ldmatrix)

typedef unsigned int u32;

static __device__ __forceinline__ u32 smem_u32(const void* p) {
    u32 a;
    asm("{ .reg .u64 t; cvta.to.shared.u64 t, %1; cvt.u32.u64 %0, t; }" : "=r"(a) : "l"(p));
    return a;
}

__global__ __launch_bounds__(TPB, 3) void conv_mma_kernel(
    const float* __restrict__ x, const float* __restrict__ pe,
    const float* __restrict__ wt, const float* __restrict__ bias,
    const float* __restrict__ rw, float* __restrict__ out, int C)
{
    __shared__ __align__(16) __half As[Hh * PAD];   // circulant weights, M x K row-major
    __shared__ __align__(16) __half Bs[Hh * PAD];   // x + pe, K x N row-major
    __shared__ __align__(16) __half wcdS[4][192];   // shift-replicated combined weights

    const int t  = threadIdx.x;
    const int bc = blockIdx.x;          // b*C + c
    const int c  = bc % C;

    const float* xp  = x + (size_t)bc * (Hh * Ww);
    const float* pep = pe + c * Hh;

    // Shift-replicated combined weights: wcdS[r][i] = wc[(i+r) mod 96], periodic in i.
    // Lets the A-fill read one aligned LDS.64 (idx mod 4 == (-h) mod 4, constant per row).
    {
        int r = t / 96, i0 = t % 96;            // t < 384 covers all (r, i0)
        int k = (i0 + r) % Hh;
        float w = wt[c * Hh + k] + (k < 3 ? rw[c * 3 + k] : 0.0f);
        __half hv = __float2half_rn(w);
        wcdS[r][i0] = hv; wcdS[r][i0 + 96] = hv;
    }

    // B fill: Bs[k][n] = fp16(x[k][n] + pe[k]),  K x N row-major, PAD stride
    #pragma unroll
    for (int i = t; i < (Hh * Ww) / 4; i += TPB) {
        float4 v = ((const float4*)xp)[i];
        int k = i / 24, n0 = (i % 24) * 4;
        float p = pep[k];
        __half2 h01 = __floats2half2_rn(v.x + p, v.y + p);
        __half2 h23 = __floats2half2_rn(v.z + p, v.w + p);
        *(uint2*)&Bs[k * PAD + n0] = make_uint2(*(u32*)&h01, *(u32*)&h23);
    }
    __syncthreads();

    // A fill: As[h][j0..j0+3] = wcbig[idx..idx+3], idx = j0-h+96 in [1,188].
    // r = idx&3, base = idx-r: wcdS[r][base+m] == wcbig[idx+m] -> one aligned LDS.64.
    #pragma unroll
    for (int i = t; i < (Hh * Ww) / 4; i += TPB) {
        int h = i / 24, j0 = (i % 24) * 4;
        int idx = j0 - h + 96;
        int r = idx & 3, base = idx - r;
        uint2 w4 = *(const uint2*)&wcdS[r][base];
        *(uint2*)&As[h * PAD + j0] = w4;
    }
    __syncthreads();

    // warp tiling: 32(M) x 24(N) per warp; B-frag shared by both m16-frags
    const int wid = t >> 5, lane = t & 31;
    const int mrow = (wid >> 2) * 32;       // 3 M-strips
    const int ncol = (wid & 3) * 24;        // 4 N-strips
    const int lr = lane & 15, lc = lane >> 4;

    const u32 sA = smem_u32(As), sB = smem_u32(Bs);
    const float bv = bias[c];

    float acc[2][3][4];
    #pragma unroll
    for (int mf = 0; mf < 2; mf++)
        #pragma unroll
        for (int n = 0; n < 3; n++)
            #pragma unroll
            for (int q = 0; q < 4; q++) acc[mf][n][q] = bv;   // bias in acc init

    #pragma unroll
    for (int k6 = 0; k6 < 6; k6++) {
        u32 a[2][4];
        #pragma unroll
        for (int mf = 0; mf < 2; mf++) {
            u32 aaddr = sA + (u32)((mrow + mf * 16 + lr) * PAD + k6 * 16 + lc * 8) * 2;
            asm volatile("ldmatrix.sync.aligned.m8n8.x4.shared.b16 {%0,%1,%2,%3}, [%4];"
                         : "=r"(a[mf][0]), "=r"(a[mf][1]), "=r"(a[mf][2]), "=r"(a[mf][3])
                         : "r"(aaddr));
        }
        #pragma unroll
        for (int n = 0; n < 3; n++) {
            u32 b0, b1;
            u32 baddr = sB + (u32)((k6 * 16 + lr) * PAD + ncol + n * 8) * 2;
            asm volatile("ldmatrix.sync.aligned.m8n8.x2.trans.shared.b16 {%0,%1}, [%2];"
                         : "=r"(b0), "=r"(b1) : "r"(baddr));
            #pragma unroll
            for (int mf = 0; mf < 2; mf++)
                asm volatile(
                    "mma.sync.aligned.m16n8k16.row.col.f32.f16.f16.f32 "
                    "{%0,%1,%2,%3}, {%4,%5,%6,%7}, {%8,%9}, {%0,%1,%2,%3};"
                    : "+f"(acc[mf][n][0]), "+f"(acc[mf][n][1]),
                      "+f"(acc[mf][n][2]), "+f"(acc[mf][n][3])
                    : "r"(a[mf][0]), "r"(a[mf][1]), "r"(a[mf][2]), "r"(a[mf][3]),
                      "r"(b0), "r"(b1));
        }
    }

    // epilogue: per m-frag, rows lane/4 and lane/4+8, cols (lane%4)*2 (direct STG.64)
    float* op = out + (size_t)bc * (Hh * Ww);
    const int rbase = mrow + (lane >> 2);
    const int col0  = ncol + (lane & 3) * 2;
    #pragma unroll
    for (int mf = 0; mf < 2; mf++) {
        const int row = rbase + mf * 16;
        #pragma unroll
        for (int n = 0; n < 3; n++) {
            *(float2*)&op[row * Ww + col0 + n * 8]       = make_float2(acc[mf][n][0], acc[mf][n][1]);
            *(float2*)&op[(row + 8) * Ww + col0 + n * 8] = make_float2(acc[mf][n][2], acc[mf][n][3]);
        }
    }
}

extern "C" void kernel_launch(void* const* d_in, const int* in_sizes, int n_in,
                              void* d_out, int out_size) {
    const float* x    = (const float*)d_in[0];
    const float* pe   = (const float*)d_in[1];
    const float* wt   = (const float*)d_in[2];
    const float* bias = (const float*)d_in[3];
    const float* rw   = (const float*)d_in[4];
    float* out = (float*)d_out;

    const int nblocks = in_sizes[0] / (Hh * Ww);  // B*C = 4096
    const int C       = in_sizes[2] / Hh;         // 256

    conv_mma_kernel<<<nblocks, TPB>>>(x, pe, wt, bias, rw, out, C);
}

// round 15
// speedup vs baseline: 1.5839x; 1.1090x over previous
#include <cuda_runtime.h>
#include <cuda_fp16.h>

#define Hh 96
#define Ww 96
#define TPB 384      // 12 warps: 3 M-strips (x32 rows) x 4 N-strips (x24 cols)
#define PAD 104      // halfs per smem row (208B stride: conflict-free ldmatrix)

typedef unsigned int u32;

static __device__ __forceinline__ u32 smem_u32(const void* p) {
    u32 a;
    asm("{ .reg .u64 t; cvta.to.shared.u64 t, %1; cvt.u32.u64 %0, t; }" : "=r"(a) : "l"(p));
    return a;
}

__global__ __launch_bounds__(TPB, 3) void conv_mma_kernel(
    const float* __restrict__ x, const float* __restrict__ pe,
    const float* __restrict__ wt, const float* __restrict__ bias,
    const float* __restrict__ rw, float* __restrict__ out, int C)
{
    __shared__ __align__(16) __half Bs[Hh * PAD];   // x + pe, K x N row-major (20KB)
    __shared__ __align__(16) u32 wpair[192];        // wpair[i] = (wcbig[i], wcbig[i+1]) fp16

    const int t  = threadIdx.x;
    const int bc = blockIdx.x;          // b*C + c
    const int c  = bc % C;

    const float* xp  = x + (size_t)bc * (Hh * Ww);
    const float* pep = pe + c * Hh;

    // wpair fill: wcbig[i] = wc[i mod 96], wc[k] = wt[c,k] + (k<3 ? rw[c,k] : 0).
    // A-frag register (h, j) == wpair[j - h + 96]; j-h+96 in [1, 191].
    if (t < 192) {
        int k1 = (t < 96) ? t : t - 96;
        int k2 = (t + 1 < 192) ? ((t + 1 < 96) ? t + 1 : t + 1 - 96) : 0;
        float w1 = wt[c * Hh + k1] + (k1 < 3 ? rw[c * 3 + k1] : 0.0f);
        float w2 = wt[c * Hh + k2] + (k2 < 3 ? rw[c * 3 + k2] : 0.0f);
        __half2 hp = __floats2half2_rn(w1, w2);
        wpair[t] = *(u32*)&hp;
    }

    // B fill: Bs[k][n] = fp16(x[k][n] + pe[k]),  K x N row-major, PAD stride
    #pragma unroll
    for (int i = t; i < (Hh * Ww) / 4; i += TPB) {
        float4 v = ((const float4*)xp)[i];
        int k = i / 24, n0 = (i % 24) * 4;
        float p = pep[k];
        __half2 h01 = __floats2half2_rn(v.x + p, v.y + p);
        __half2 h23 = __floats2half2_rn(v.z + p, v.w + p);
        *(uint2*)&Bs[k * PAD + n0] = make_uint2(*(u32*)&h01, *(u32*)&h23);
    }
    __syncthreads();            // single prep barrier

    // warp tiling: 32(M) x 24(N) per warp; B-frag shared by both m16-frags
    const int wid = t >> 5, lane = t & 31;
    const int mrow = (wid >> 2) * 32;       // 3 M-strips
    const int ncol = (wid & 3) * 24;        // 4 N-strips
    const int lr = lane & 15;

    const u32 sB = smem_u32(Bs);
    const float bv = bias[c];

    // A-frag base index: reg a0 of (mf=0, k6=0) reads wpair[cbase - hrow + 96]
    const int hrow  = mrow + (lane >> 2);   // fragment row (mf=0)
    const int cbase = (lane & 3) * 2;       // fragment k-col
    const int ib = cbase - hrow + 96;       // + k6*16 (+8 for a2/a3) (-8 row, -16 mf)

    float acc[2][3][4];
    #pragma unroll
    for (int mf = 0; mf < 2; mf++)
        #pragma unroll
        for (int n = 0; n < 3; n++)
            #pragma unroll
            for (int q = 0; q < 4; q++) acc[mf][n][q] = bv;   // bias in acc init

    #pragma unroll
    for (int k6 = 0; k6 < 6; k6++) {
        // A fragments straight from the pair table (no As tile, no ldmatrix):
        // a0:(h, j) a1:(h+8, j) a2:(h, j+8) a3:(h+8, j+8); value = wpair[j-h+96]
        u32 a[2][4];
        #pragma unroll
        for (int mf = 0; mf < 2; mf++) {
            int i0 = ib + k6 * 16 - mf * 16;
            a[mf][0] = wpair[i0];
            a[mf][1] = wpair[i0 - 8];
            a[mf][2] = wpair[i0 + 8];
            a[mf][3] = wpair[i0];          // (h+8, j+8) == (h, j) shift -> same entry
        }
        #pragma unroll
        for (int n = 0; n < 3; n++) {
            u32 b0, b1;
            u32 baddr = sB + (u32)((k6 * 16 + lr) * PAD + ncol + n * 8) * 2;
            asm volatile("ldmatrix.sync.aligned.m8n8.x2.trans.shared.b16 {%0,%1}, [%2];"
                         : "=r"(b0), "=r"(b1) : "r"(baddr));
            #pragma unroll
            for (int mf = 0; mf < 2; mf++)
                asm volatile(
                    "mma.sync.aligned.m16n8k16.row.col.f32.f16.f16.f32 "
                    "{%0,%1,%2,%3}, {%4,%5,%6,%7}, {%8,%9}, {%0,%1,%2,%3};"
                    : "+f"(acc[mf][n][0]), "+f"(acc[mf][n][1]),
                      "+f"(acc[mf][n][2]), "+f"(acc[mf][n][3])
                    : "r"(a[mf][0]), "r"(a[mf][1]), "r"(a[mf][2]), "r"(a[mf][3]),
                      "r"(b0), "r"(b1));
        }
    }

    // epilogue: per m-frag, rows lane/4 and lane/4+8, cols (lane%4)*2 (direct STG.64)
    float* op = out + (size_t)bc * (Hh * Ww);
    const int rbase = mrow + (lane >> 2);
    const int col0  = ncol + (lane & 3) * 2;
    #pragma unroll
    for (int mf = 0; mf < 2; mf++) {
        const int row = rbase + mf * 16;
        #pragma unroll
        for (int n = 0; n < 3; n++) {
            *(float2*)&op[row * Ww + col0 + n * 8]       = make_float2(acc[mf][n][0], acc[mf][n][1]);
            *(float2*)&op[(row + 8) * Ww + col0 + n * 8] = make_float2(acc[mf][n][2], acc[mf][n][3]);
        }
    }
}

extern "C" void kernel_launch(void* const* d_in, const int* in_sizes, int n_in,
                              void* d_out, int out_size) {
    const float* x    = (const float*)d_in[0];
    const float* pe   = (const float*)d_in[1];
    const float* wt   = (const float*)d_in[2];
    const float* bias = (const float*)d_in[3];
    const float* rw   = (const float*)d_in[4];
    float* out = (float*)d_out;

    const int nblocks = in_sizes[0] / (Hh * Ww);  // B*C = 4096
    const int C       = in_sizes[2] / Hh;         // 256

    conv_mma_kernel<<<nblocks, TPB>>>(x, pe, wt, bias, rw, out, C);
}